// round 7
// baseline (speedup 1.0000x reference)
#include <cuda_runtime.h>
#include <cuda_bf16.h>
#include <cstdint>

#define NB 8
#define CC 256
#define NN 4096
#define DD 32
#define BQ 64
#define BK 64
#define NT (NN / BK)

// Pre-split bf16 operands (hi + lo ~ fp32-grade with 3-term products)
__device__ __align__(128) __nv_bfloat16 g_qh[(size_t)NB * NN * DD];
__device__ __align__(128) __nv_bfloat16 g_ql[(size_t)NB * NN * DD];
__device__ __align__(128) __nv_bfloat16 g_kh[(size_t)NB * NN * DD];
__device__ __align__(128) __nv_bfloat16 g_kl[(size_t)NB * NN * DD];
__device__ __align__(128) __nv_bfloat16 g_vh[(size_t)NB * CC * NN];  // [b][c][n]
__device__ __align__(128) __nv_bfloat16 g_vl[(size_t)NB * CC * NN];

// ---- smem byte offsets (dynamic smem) ----
#define QSTR 80                    // 32 bf16 row + pad (20 words, ≡4 mod 32... 20%32=20; conflict-free per-phase)
#define VSTR 144                   // 64 bf16 row + pad (36 words ≡ 4 mod 32)
#define PSTR 144                   // 64 bf16 row + pad
#define OSTR 260                   // stage stride in floats
#define QH_OFF 0
#define QL_OFF 5120
#define K_OFF(buf, mat) (10240 + (buf) * 10240 + (mat) * 5120)
#define PH_OFF 30720               // 64 q x 64 m bf16, 9216 B
#define PL_OFF 39936
#define V_OFF(buf, mat) (49152 + (buf) * 73728 + (mat) * 36864)
#define STAGE_OFF 49152            // reuses V buf0 region at epilogue
#define SMEM_BYTES 196608

// ---- helpers ----
__device__ __forceinline__ uint32_t smem_u32(const void* p) {
    uint32_t a;
    asm("{ .reg .u64 t; cvta.to.shared.u64 t, %1; cvt.u32.u64 %0, t; }" : "=r"(a) : "l"(p));
    return a;
}
__device__ __forceinline__ void cpa16(uint32_t dst, const void* src) {
    asm volatile("cp.async.cg.shared.global [%0], [%1], 16;" :: "r"(dst), "l"(src) : "memory");
}
__device__ __forceinline__ void cp_commit() { asm volatile("cp.async.commit_group;" ::: "memory"); }
template <int N> __device__ __forceinline__ void cp_wait() {
    asm volatile("cp.async.wait_group %0;" :: "n"(N) : "memory");
}
__device__ __forceinline__ void mma_bf16(float* d, const uint32_t* a, const uint32_t* b) {
    asm volatile(
        "mma.sync.aligned.m16n8k16.row.col.f32.bf16.bf16.f32 "
        "{%0,%1,%2,%3}, {%4,%5,%6,%7}, {%8,%9}, {%0,%1,%2,%3};"
        : "+f"(d[0]), "+f"(d[1]), "+f"(d[2]), "+f"(d[3])
        : "r"(a[0]), "r"(a[1]), "r"(a[2]), "r"(a[3]), "r"(b[0]), "r"(b[1]));
}
__device__ __forceinline__ void ldmx4(uint32_t* r, uint32_t a) {
    asm volatile("ldmatrix.sync.aligned.m8n8.x4.shared.b16 {%0,%1,%2,%3}, [%4];"
        : "=r"(r[0]), "=r"(r[1]), "=r"(r[2]), "=r"(r[3]) : "r"(a));
}
__device__ __forceinline__ uint32_t packbf(__nv_bfloat16 lo, __nv_bfloat16 hi) {
    __nv_bfloat162 t; t.x = lo; t.y = hi;
    return *(uint32_t*)&t;
}

// per-thread share of one K/V tile load (18 cp.async of 16B)
__device__ __forceinline__ void load_kv(char* smp, int b, int m0, int buf, int tid) {
#pragma unroll
    for (int it = 0; it < 2; it++) {            // K: 64 rows x 4 chunks x 2 mats
        int idx = tid + it * 256;
        int mat = idx >> 8, r = (idx >> 2) & 63, j = idx & 3;
        const __nv_bfloat16* src = (mat ? g_kl : g_kh) +
            ((size_t)(b * NN + m0 + r)) * DD + j * 8;
        cpa16(smem_u32(smp + K_OFF(buf, mat) + r * QSTR + j * 16), src);
    }
#pragma unroll
    for (int it = 0; it < 16; it++) {           // V: 256 rows x 8 chunks x 2 mats
        int idx = tid + it * 256;
        int mat = idx >> 11, r = (idx >> 3) & 255, j = idx & 7;
        const __nv_bfloat16* src = (mat ? g_vl : g_vh) +
            ((size_t)(b * CC + r)) * NN + m0 + j * 8;
        cpa16(smem_u32(smp + V_OFF(buf, mat) + r * VSTR + j * 16), src);
    }
}

// ---------------------------------------------------------------------------
// Projection: q/k -> [b][n][32] bf16 hi/lo
// ---------------------------------------------------------------------------
__global__ void __launch_bounds__(256) proj_qk(
    const float* __restrict__ W, const float* __restrict__ bias,
    const float* __restrict__ x,
    __nv_bfloat16* __restrict__ oh, __nv_bfloat16* __restrict__ ol)
{
    __shared__ float xs[32][128];
    __shared__ float ws[32][33];
    const int tid = threadIdx.x;
    const int b  = blockIdx.y;
    const int n0 = blockIdx.x * 128;
    const int tr = tid & 7, tn = tid >> 3;

    float acc[4][4];
#pragma unroll
    for (int i = 0; i < 4; i++) {
        float bb = bias[tr * 4 + i];
#pragma unroll
        for (int j = 0; j < 4; j++) acc[i][j] = bb;
    }
    for (int c0 = 0; c0 < CC; c0 += 32) {
#pragma unroll
        for (int k = 0; k < 16; k++) {
            int idx = tid + k * 256;
            int row = idx >> 7, col = idx & 127;
            xs[row][col] = x[((size_t)b * CC + (c0 + row)) * NN + n0 + col];
        }
#pragma unroll
        for (int k = 0; k < 4; k++) {
            int idx = tid + k * 256;
            int row = idx >> 5, col = idx & 31;
            ws[row][col] = W[(size_t)row * CC + c0 + col];
        }
        __syncthreads();
#pragma unroll 8
        for (int cc = 0; cc < 32; cc++) {
            float4 xv = *(const float4*)&xs[cc][tn * 4];
            float wr[4];
#pragma unroll
            for (int i = 0; i < 4; i++) wr[i] = ws[tr * 4 + i][cc];
#pragma unroll
            for (int i = 0; i < 4; i++) {
                acc[i][0] += wr[i] * xv.x; acc[i][1] += wr[i] * xv.y;
                acc[i][2] += wr[i] * xv.z; acc[i][3] += wr[i] * xv.w;
            }
        }
        __syncthreads();
    }
#pragma unroll
    for (int j = 0; j < 4; j++) {
        int n = n0 + tn * 4 + j;
#pragma unroll
        for (int i = 0; i < 4; i++) {
            int r = tr * 4 + i;
            float a = acc[i][j];
            __nv_bfloat16 h = __float2bfloat16(a);
            oh[((size_t)(b * NN + n)) * DD + r] = h;
            ol[((size_t)(b * NN + n)) * DD + r] = __float2bfloat16(a - __bfloat162float(h));
        }
    }
}

// ---------------------------------------------------------------------------
// Projection: v -> [b][c][n] bf16 hi/lo
// ---------------------------------------------------------------------------
__global__ void __launch_bounds__(256) proj_v(
    const float* __restrict__ W, const float* __restrict__ bias,
    const float* __restrict__ x,
    __nv_bfloat16* __restrict__ oh, __nv_bfloat16* __restrict__ ol)
{
    __shared__ float xs[32][128];
    __shared__ float ws[32][33];
    const int tid = threadIdx.x;
    const int b  = blockIdx.y;
    const int n0 = blockIdx.x * 128;
    const int r0 = blockIdx.z * 32;
    const int tr = tid & 7, tn = tid >> 3;

    float acc[4][4];
#pragma unroll
    for (int i = 0; i < 4; i++) {
        float bb = bias[r0 + tr * 4 + i];
#pragma unroll
        for (int j = 0; j < 4; j++) acc[i][j] = bb;
    }
    for (int c0 = 0; c0 < CC; c0 += 32) {
#pragma unroll
        for (int k = 0; k < 16; k++) {
            int idx = tid + k * 256;
            int row = idx >> 7, col = idx & 127;
            xs[row][col] = x[((size_t)b * CC + (c0 + row)) * NN + n0 + col];
        }
#pragma unroll
        for (int k = 0; k < 4; k++) {
            int idx = tid + k * 256;
            int row = idx >> 5, col = idx & 31;
            ws[row][col] = W[(size_t)(r0 + row) * CC + c0 + col];
        }
        __syncthreads();
#pragma unroll 8
        for (int cc = 0; cc < 32; cc++) {
            float4 xv = *(const float4*)&xs[cc][tn * 4];
            float wr[4];
#pragma unroll
            for (int i = 0; i < 4; i++) wr[i] = ws[tr * 4 + i][cc];
#pragma unroll
            for (int i = 0; i < 4; i++) {
                acc[i][0] += wr[i] * xv.x; acc[i][1] += wr[i] * xv.y;
                acc[i][2] += wr[i] * xv.z; acc[i][3] += wr[i] * xv.w;
            }
        }
        __syncthreads();
    }
#pragma unroll
    for (int i = 0; i < 4; i++) {
        int r = r0 + tr * 4 + i;
#pragma unroll
        for (int j = 0; j < 4; j++) {
            int n = n0 + tn * 4 + j;
            float a = acc[i][j];
            __nv_bfloat16 h = __float2bfloat16(a);
            oh[((size_t)(b * CC + r)) * NN + n] = h;
            ol[((size_t)(b * CC + r)) * NN + n] = __float2bfloat16(a - __bfloat162float(h));
        }
    }
}

// ---------------------------------------------------------------------------
// Flash attention via mma.sync + ldmatrix, split-S with P smem exchange.
// Grid (NN/BQ, NB) = (64, 8); 256 threads = 8 warps in (4 q-rows x 2 c-halves).
// ---------------------------------------------------------------------------
__global__ void __launch_bounds__(256, 1) flash_mma(
    const float* __restrict__ x, const float* __restrict__ gamma,
    float* __restrict__ out)
{
    extern __shared__ char smp[];
    const int tid  = threadIdx.x;
    const int wid  = tid >> 5;
    const int lane = tid & 31;
    const int wr   = wid >> 1;        // 0..3: q-rows  wr*16..+15
    const int wc   = wid & 1;         // 0..1: c-half (also key-half for S)
    const int g    = lane >> 2;       // groupID
    const int tg   = lane & 3;        // threadID-in-group
    const int b  = blockIdx.y;
    const int q0 = blockIdx.x * BQ;

    // ---- prologue: Q + tile-0 K/V ----
#pragma unroll
    for (int it = 0; it < 2; it++) {       // Q: 64 rows x 4 chunks x 2 mats
        int idx = tid + it * 256;
        int mat = idx >> 8, r = (idx >> 2) & 63, j = idx & 3;
        const __nv_bfloat16* src = (mat ? g_ql : g_qh) +
            ((size_t)(b * NN + q0 + r)) * DD + j * 8;
        cpa16(smem_u32(smp + (mat ? QL_OFF : QH_OFF) + r * QSTR + j * 16), src);
    }
    load_kv(smp, b, 0, 0, tid);
    cp_commit();
    cp_wait<0>();
    __syncthreads();

    // ---- preload Q A-fragments via ldmatrix (constant across tiles) ----
    uint32_t QhA[2][4], QlA[2][4];
    {
        uint32_t qa = smem_u32(smp + QH_OFF) +
            (uint32_t)((wr * 16 + (lane & 15)) * QSTR + ((lane >> 4) & 1) * 16);
        ldmx4(QhA[0], qa);
        ldmx4(QhA[1], qa + 32);
        ldmx4(QlA[0], qa + (QL_OFF - QH_OFF));
        ldmx4(QlA[1], qa + (QL_OFF - QH_OFF) + 32);
    }

    float O[16][4];
#pragma unroll
    for (int i = 0; i < 16; i++)
#pragma unroll
        for (int j = 0; j < 4; j++) O[i][j] = 0.f;
    float lsumA = 0.f, lsumB = 0.f;

    // loop-invariant addresses
    const int mt0 = wc * 32;                         // this warp's key half
    char* pA_h = smp + PH_OFF + (wr * 16 + g) * PSTR + (mt0 + 2 * tg) * 2;
    char* pA_l = pA_h + (PL_OFF - PH_OFF);
    const uint32_t pa = smem_u32(smp + PH_OFF) +
        (uint32_t)((wr * 16 + (lane & 15)) * PSTR + ((lane >> 4) & 1) * 16);

    for (int t = 0; t < NT; t++) {
        const int buf = t & 1;
        if (t) cp_wait<0>();
        __syncthreads();
        if (t + 1 < NT) { load_kv(smp, b, (t + 1) * BK, buf ^ 1, tid); cp_commit(); }

        // ---- S = Q K^T on this warp's 32 keys; exp; P -> smem ----
        {
            uint32_t ka = smem_u32(smp + K_OFF(buf, 0)) +
                (uint32_t)((mt0 + (lane & 7)) * QSTR + (lane >> 3) * 16);
#pragma unroll
            for (int nt = 0; nt < 4; nt++) {
                uint32_t KhB[4], KlB[4];
                ldmx4(KhB, ka + nt * 8 * QSTR);
                ldmx4(KlB, ka + nt * 8 * QSTR + 5120);
                float S[4] = {0.f, 0.f, 0.f, 0.f};
                mma_bf16(S, QhA[0], KhB);     mma_bf16(S, QhA[1], KhB + 2);
                mma_bf16(S, QlA[0], KhB);     mma_bf16(S, QlA[1], KhB + 2);
                mma_bf16(S, QhA[0], KlB);     mma_bf16(S, QhA[1], KlB + 2);

                float p0 = __expf(S[0]), p1 = __expf(S[1]);
                float p2 = __expf(S[2]), p3 = __expf(S[3]);
                lsumA += p0 + p1;
                lsumB += p2 + p3;
                __nv_bfloat16 h0 = __float2bfloat16(p0), h1 = __float2bfloat16(p1);
                __nv_bfloat16 h2 = __float2bfloat16(p2), h3 = __float2bfloat16(p3);
                *(uint32_t*)(pA_h + nt * 16)             = packbf(h0, h1);
                *(uint32_t*)(pA_h + 8 * PSTR + nt * 16)  = packbf(h2, h3);
                *(uint32_t*)(pA_l + nt * 16) =
                    packbf(__float2bfloat16(p0 - __bfloat162float(h0)),
                           __float2bfloat16(p1 - __bfloat162float(h1)));
                *(uint32_t*)(pA_l + 8 * PSTR + nt * 16) =
                    packbf(__float2bfloat16(p2 - __bfloat162float(h2)),
                           __float2bfloat16(p3 - __bfloat162float(h3)));
            }
        }
        __syncthreads();

        // ---- reload full-width P as A-fragments ----
        uint32_t Ph[4][4], Pl[4][4];
#pragma unroll
        for (int kf = 0; kf < 4; kf++) {
            ldmx4(Ph[kf], pa + kf * 32);
            ldmx4(Pl[kf], pa + (PL_OFF - PH_OFF) + kf * 32);
        }

        // ---- O += P V^T ----
        {
            uint32_t va = smem_u32(smp + V_OFF(buf, 0)) +
                (uint32_t)((wc * 128 + (lane & 7)) * VSTR + (lane >> 3) * 16);
#pragma unroll
            for (int nt = 0; nt < 16; nt++) {
                uint32_t Vh[8], Vl[8];
                ldmx4(Vh,     va + nt * 8 * VSTR);
                ldmx4(Vh + 4, va + nt * 8 * VSTR + 64);
                ldmx4(Vl,     va + nt * 8 * VSTR + 36864);
                ldmx4(Vl + 4, va + nt * 8 * VSTR + 36864 + 64);
#pragma unroll
                for (int kf = 0; kf < 4; kf++) {
                    mma_bf16(O[nt], Ph[kf], Vh + kf * 2);
                    mma_bf16(O[nt], Pl[kf], Vh + kf * 2);
                    mma_bf16(O[nt], Ph[kf], Vl + kf * 2);
                }
            }
        }
    }

    // ---- combine lsum partials (quad shuffle + cross-warp via smem) ----
    lsumA += __shfl_xor_sync(0xffffffffu, lsumA, 1);
    lsumA += __shfl_xor_sync(0xffffffffu, lsumA, 2);
    lsumB += __shfl_xor_sync(0xffffffffu, lsumB, 1);
    lsumB += __shfl_xor_sync(0xffffffffu, lsumB, 2);

    __syncthreads();                       // all P/V reads finished
    float* lsh = (float*)(smp + PH_OFF);   // 128 floats: [ch][q]
    if (tg == 0) {
        lsh[wc * 64 + wr * 16 + g]     = lsumA;
        lsh[wc * 64 + wr * 16 + 8 + g] = lsumB;
    }
    // stage unnormalized O
    float* stage = (float*)(smp + STAGE_OFF);
    {
        int q = wr * 16 + g;
#pragma unroll
        for (int nt = 0; nt < 16; nt++) {
            int c = wc * 128 + nt * 8 + tg * 2;
            stage[q * OSTR + c]           = O[nt][0];
            stage[q * OSTR + c + 1]       = O[nt][1];
            stage[(q + 8) * OSTR + c]     = O[nt][2];
            stage[(q + 8) * OSTR + c + 1] = O[nt][3];
        }
    }
    __syncthreads();
    const float gm = gamma[0];
    if (tid < 64) lsh[tid] = gm / (lsh[tid] + lsh[64 + tid]);   // per-q scale
    __syncthreads();

    {
        int c = tid;   // one channel row per thread
        const float* xr  = x   + ((size_t)(b * CC + c)) * NN + q0;
        float*       orw = out + ((size_t)(b * CC + c)) * NN + q0;
#pragma unroll 4
        for (int n4 = 0; n4 < 16; n4++) {
            float4 xv = *(const float4*)(xr + n4 * 4);
            float4 o;
            o.x = stage[(n4 * 4 + 0) * OSTR + c] * lsh[n4 * 4 + 0] + xv.x;
            o.y = stage[(n4 * 4 + 1) * OSTR + c] * lsh[n4 * 4 + 1] + xv.y;
            o.z = stage[(n4 * 4 + 2) * OSTR + c] * lsh[n4 * 4 + 2] + xv.z;
            o.w = stage[(n4 * 4 + 3) * OSTR + c] * lsh[n4 * 4 + 3] + xv.w;
            *(float4*)(orw + n4 * 4) = o;
        }
    }
}

// ---------------------------------------------------------------------------
extern "C" void kernel_launch(void* const* d_in, const int* in_sizes, int n_in,
                              void* d_out, int out_size)
{
    const float* x     = (const float*)d_in[0];
    const float* wq    = (const float*)d_in[1];
    const float* bq    = (const float*)d_in[2];
    const float* wk    = (const float*)d_in[3];
    const float* bk    = (const float*)d_in[4];
    const float* wv    = (const float*)d_in[5];
    const float* bv    = (const float*)d_in[6];
    const float* gamma = (const float*)d_in[7];
    float* out = (float*)d_out;

    __nv_bfloat16 *qh, *ql, *kh, *kl, *vh, *vl;
    cudaGetSymbolAddress((void**)&qh, g_qh);
    cudaGetSymbolAddress((void**)&ql, g_ql);
    cudaGetSymbolAddress((void**)&kh, g_kh);
    cudaGetSymbolAddress((void**)&kl, g_kl);
    cudaGetSymbolAddress((void**)&vh, g_vh);
    cudaGetSymbolAddress((void**)&vl, g_vl);

    dim3 blk(256);
    proj_qk<<<dim3(NN / 128, NB), blk>>>(wq, bq, x, qh, ql);
    proj_qk<<<dim3(NN / 128, NB), blk>>>(wk, bk, x, kh, kl);
    proj_v <<<dim3(NN / 128, NB, CC / 32), blk>>>(wv, bv, x, vh, vl);

    cudaFuncSetAttribute(flash_mma, cudaFuncAttributeMaxDynamicSharedMemorySize, SMEM_BYTES);
    flash_mma<<<dim3(NN / BQ, NB), blk, SMEM_BYTES>>>(x, gamma, out);
}